// round 17
// baseline (speedup 1.0000x reference)
#include <cuda_runtime.h>
#include <math_constants.h>

#define NN    10000
#define EE    160000
#define SNAP  16       // B*T
#define TT    8
#define BB    2
#define CIN   64
#define CC    32
#define SLOTS 96       // padded bucket capacity per node (max degree ~40)
#define XCH   256      // rows per xlr block
#define XPAD  66       // smem row stride (floats): 2-way max bank conflicts

typedef unsigned long long u64;
#define F2FMA(r, x, y, z) asm("fma.rn.f32x2 %0,%1,%2,%3;" : "=l"(r) : "l"(x), "l"(y), "l"(z))
#define F2PK(r, lo, hi)   asm("mov.b64 %0,{%1,%2};"       : "=l"(r) : "f"(lo), "f"(hi))
#define F2UNPK(lo, hi, x) asm("mov.b64 {%0,%1},%2;"       : "=f"(lo), "=f"(hi) : "l"(x))

// ---------------- static device scratch (zero-initialized at load) ----------------
__device__ float g_xl[NN * SNAP * CC];       // [n][s][c]
__device__ float g_xr[NN * SNAP * CC];       // [n][s][c]
__device__ float g_loop_sum[NN * 3];
__device__ int   g_cursor[NN];               // per-node in-degree / bucket cursor
__device__ int4  g_bkt[NN * SLOTS];          // {src, attr0, attr1, attr2}

// ---------------- build: bucket scatter + loop_sum in ONE kernel ----------------
__global__ void k_build(const int* __restrict__ ei, const float* __restrict__ ea) {
    int e = blockIdx.x * blockDim.x + threadIdx.x;
    if (e >= EE) return;
    int src = ei[e];
    int dst = ei[EE + e];
    float a0 = ea[e * 3 + 0], a1 = ea[e * 3 + 1], a2 = ea[e * 3 + 2];
    atomicAdd(&g_loop_sum[dst * 3 + 0], a0);
    atomicAdd(&g_loop_sum[dst * 3 + 1], a1);
    atomicAdd(&g_loop_sum[dst * 3 + 2], a2);
    int pos = atomicAdd(&g_cursor[dst], 1);
    g_bkt[dst * SLOTS + pos] =
        make_int4(src, __float_as_int(a0), __float_as_int(a1), __float_as_int(a2));
}

// ---------------- xlr v4: lane = row, packed f32x2 channel pairs ----------------
// sW[k][i] = {wl(2i), wl(2i+1), wr(2i), wr(2i+1)}: one LDS.128 -> two packed
// f32x2 operands. acc = 32 packed channel pairs (16 l + 16 r). x broadcast
// duplicated once per k. FMA count halves vs scalar.
__global__ void __launch_bounds__(256) k_xlr(const float* __restrict__ x,
                      const float* __restrict__ W_l, const float* __restrict__ b_l,
                      const float* __restrict__ W_r, const float* __restrict__ b_r) {
    extern __shared__ float sx[];            // [XCH][XPAD]
    __shared__ float4 sW[CIN][16];           // [k][i] = {wl2i, wl2i+1, wr2i, wr2i+1}
    __shared__ float4 sB[16];                // [i] = {bl2i, bl2i+1, br2i, br2i+1}

    int tid = threadIdx.x;
    for (int i = tid; i < CIN * 16; i += 256) {
        int k = i >> 4, cp = i & 15;
        sW[k][cp] = make_float4(W_l[k * 32 + 2 * cp], W_l[k * 32 + 2 * cp + 1],
                                W_r[k * 32 + 2 * cp], W_r[k * 32 + 2 * cp + 1]);
    }
    if (tid < 16)
        sB[tid] = make_float4(b_l[2 * tid], b_l[2 * tid + 1],
                              b_r[2 * tid], b_r[2 * tid + 1]);

    int rbase = blockIdx.x * XCH;            // grid 625 exact
    {
        const float2* xg = (const float2*)(x + (long)rbase * CIN);
        for (int i = tid; i < XCH * 32; i += 256) {
            int row = i >> 5, q = i & 31;
            *(float2*)&sx[row * XPAD + q * 2] = xg[row * 32 + q];
        }
    }
    __syncthreads();

    int w = tid >> 5, lane = tid & 31;
    int rloc = w * 32 + lane;
    int rglob = rbase + rloc;

    u64 accl[16], accr[16];                  // packed channel pairs
#pragma unroll
    for (int i = 0; i < 16; i++) {
        float4 b = sB[i];
        F2PK(accl[i], b.x, b.y);
        F2PK(accr[i], b.z, b.w);
    }

    const float* xrow = &sx[rloc * XPAD];
#pragma unroll 4
    for (int k = 0; k < CIN; k++) {
        float xk = xrow[k];
        u64 xd;
        F2PK(xd, xk, xk);
#pragma unroll
        for (int i = 0; i < 16; i++) {
            ulonglong2 wv = *(const ulonglong2*)&sW[k][i];  // {wl pair, wr pair}
            F2FMA(accl[i], xd, wv.x, accl[i]);
            F2FMA(accr[i], xd, wv.y, accr[i]);
        }
    }

    int s = rglob / NN, n = rglob - s * NN;
    u64* outl = (u64*)(g_xl + (n * SNAP + s) * 32);
    u64* outr = (u64*)(g_xr + (n * SNAP + s) * 32);
#pragma unroll
    for (int i = 0; i < 16; i++) {
        outl[i] = accl[i];
        outr[i] = accr[i];
    }
}

// Dynamic-smem layout for k_gatgru
struct GGSmem {
    float4 sWA[32][32];     // [h][c] = {wi_r, wh_r, wi_z, wh_z}   16KB
    float2 sWB[32][32];     // [h][c] = {wi_n, wh_n}                8KB
    float2 s_tr[16][8][32]; // [nodeLocal][t][c] = {b0, b1}        32KB
    float2 s_h[8][2][32];   // [warp][nodeSel][c]                   2KB
    float  sb[6][32];
    float4 swe[3][8];
    float4 sat[8];
};

// Fused GATv2 + GRU (unchanged from round 16 best).
__global__ void __launch_bounds__(256, 2) k_gatgru(
        const float* __restrict__ W_e,
        const float* __restrict__ att, const float* __restrict__ bias_gat,
        const float* __restrict__ W_ih, const float* __restrict__ W_hh,
        const float* __restrict__ b_ih, const float* __restrict__ b_hh,
        float* __restrict__ out) {
    extern __shared__ char ggsm_raw[];
    GGSmem& S = *reinterpret_cast<GGSmem*>(ggsm_raw);

    int tid = threadIdx.x;
    for (int i = tid; i < 1024; i += 256) {
        int c = i & 31, hh = i >> 5;
        S.sWA[hh][c] = make_float4(W_ih[c * 32 + hh],        W_hh[c * 32 + hh],
                                   W_ih[(32 + c) * 32 + hh], W_hh[(32 + c) * 32 + hh]);
        S.sWB[hh][c] = make_float2(W_ih[(64 + c) * 32 + hh], W_hh[(64 + c) * 32 + hh]);
    }
    if (tid < 96) {
        int g = tid >> 5, c = tid & 31;
        S.sb[g][c] = b_ih[tid];
        S.sb[3 + g][c] = b_hh[tid];
    }
    if (tid < 24) S.swe[tid >> 3][tid & 7] = ((const float4*)W_e)[(tid >> 3) * 8 + (tid & 7)];
    if (tid < 8) S.sat[tid] = ((const float4*)att)[tid];
    __syncthreads();

    int w = tid >> 5, lane = tid & 31;
    int nbase = blockIdx.x * 16 + w * 2;   // grid = NN/16 exact
    int q = lane & 7, g = lane >> 3;

#define GAT_EDGE(A, EB, VALID)                                              \
    do {                                                                    \
        float a0 = __int_as_float(EB.y);                                    \
        float a1 = __int_as_float(EB.z);                                    \
        float a2 = __int_as_float(EB.w);                                    \
        float4 w0 = S.swe[0][q], w1 = S.swe[1][q], w2 = S.swe[2][q];        \
        float4 at4 = S.sat[q];                                              \
        float4 ev;                                                          \
        ev.x = a0 * w0.x + a1 * w1.x + a2 * w2.x;                           \
        ev.y = a0 * w0.y + a1 * w1.y + a2 * w2.y;                           \
        ev.z = a0 * w0.z + a1 * w1.z + a2 * w2.z;                           \
        ev.w = a0 * w0.w + a1 * w1.w + a2 * w2.w;                           \
        float d[4];                                                         \
        _Pragma("unroll")                                                   \
        for (int k = 0; k < 4; k++) {                                       \
            float v0 = A[k].x + ev.x + xr4[k].x;                            \
            float v1 = A[k].y + ev.y + xr4[k].y;                            \
            float v2 = A[k].z + ev.z + xr4[k].z;                            \
            float v3 = A[k].w + ev.w + xr4[k].w;                            \
            v0 = fmaxf(v0, 0.2f * v0);                                      \
            v1 = fmaxf(v1, 0.2f * v1);                                      \
            v2 = fmaxf(v2, 0.2f * v2);                                      \
            v3 = fmaxf(v3, 0.2f * v3);                                      \
            d[k] = v0 * at4.x + v1 * at4.y + v2 * at4.z + v3 * at4.w;       \
        }                                                                   \
        _Pragma("unroll")                                                   \
        for (int o = 1; o < 8; o <<= 1) {                                   \
            _Pragma("unroll")                                               \
            for (int k = 0; k < 4; k++)                                     \
                d[k] += __shfl_xor_sync(0xffffffffu, d[k], o);              \
        }                                                                   \
        _Pragma("unroll")                                                   \
        for (int k = 0; k < 4; k++) {                                       \
            float wv = (VALID) ? __expf(d[k]) : 0.f;                        \
            ssum[k] += wv;                                                  \
            acc[k].x += wv * A[k].x;                                        \
            acc[k].y += wv * A[k].y;                                        \
            acc[k].z += wv * A[k].z;                                        \
            acc[k].w += wv * A[k].w;                                        \
        }                                                                   \
    } while (0)

    for (int i = 0; i < 2; i++) {
        int n = nbase + i;
        int deg = g_cursor[n];

        float4 xr4[4];
        {
            const float4* p = (const float4*)(g_xr + n * SNAP * 32);
#pragma unroll
            for (int k = 0; k < 4; k++) xr4[k] = p[k * 32 + lane];
        }
        float4 acc[4];
#pragma unroll
        for (int k = 0; k < 4; k++) acc[k] = make_float4(0.f, 0.f, 0.f, 0.f);
        float ssum[4] = {0.f, 0.f, 0.f, 0.f};

        const int4* bkt = g_bkt + n * SLOTS;

        if (deg > 0) {
            int4 eb0 = bkt[0];
            float4 a[4];
            {
                const float4* xp = (const float4*)(g_xl + eb0.x * SNAP * 32);
#pragma unroll
                for (int k = 0; k < 4; k++) a[k] = xp[k * 32 + lane];
            }
            for (int j = 0; j < deg; j += 2) {
                int j1 = (j + 1 < deg) ? j + 1 : j;
                int4 eb1 = bkt[j1];
                const float4* xp1 = (const float4*)(g_xl + eb1.x * SNAP * 32);
                float4 an[4];
#pragma unroll
                for (int k = 0; k < 4; k++) an[k] = xp1[k * 32 + lane];

                GAT_EDGE(a, eb0, true);

                int j2 = (j + 2 < deg) ? j + 2 : deg - 1;
                eb0 = bkt[j2];
                const float4* xp2 = (const float4*)(g_xl + eb0.x * SNAP * 32);
#pragma unroll
                for (int k = 0; k < 4; k++) a[k] = xp2[k * 32 + lane];

                GAT_EDGE(an, eb1, (j + 1 < deg));
            }
        }

        // self-loop tail (attrs = segment mean; src = n)
        {
            float invc = 1.f / fmaxf((float)deg, 1.f);
            int4 ebs = make_int4(n,
                __float_as_int(g_loop_sum[n * 3 + 0] * invc),
                __float_as_int(g_loop_sum[n * 3 + 1] * invc),
                __float_as_int(g_loop_sum[n * 3 + 2] * invc));
            const float4* xps = (const float4*)(g_xl + n * SNAP * 32);
            float4 as[4];
#pragma unroll
            for (int k = 0; k < 4; k++) as[k] = xps[k * 32 + lane];
            GAT_EDGE(as, ebs, true);
        }

        // write normalized + biased result into transpose buffer
        {
            const float4 bi4 = *(const float4*)(bias_gat + 4 * q);
            int nl = w * 2 + i;
#pragma unroll
            for (int k = 0; k < 4; k++) {
                float inv = 1.f / ssum[k];
                int s = 4 * k + g;
                int b = s >> 3, t = s & 7;
                float* tp = (float*)&S.s_tr[nl][t][4 * q];
                tp[0 * 2 + b] = acc[k].x * inv + bi4.x;
                tp[1 * 2 + b] = acc[k].y * inv + bi4.y;
                tp[2 * 2 + b] = acc[k].z * inv + bi4.z;
                tp[3 * 2 + b] = acc[k].w * inv + bi4.w;
            }
        }
    }
#undef GAT_EDGE
    __syncwarp();

    // ---- GRU phase: lane = channel c; 4 sequences (2 nodes x 2 batches)
    int c = lane;
    int nl0 = w * 2, nl1 = w * 2 + 1;
    int n0 = nbase, n1 = nbase + 1;
    u64 GR, GZ, GIN, GHN;
    {
        float br_ = S.sb[0][c] + S.sb[3][c];
        float bz_ = S.sb[1][c] + S.sb[4][c];
        float bn_i = S.sb[2][c];
        float bn_h = S.sb[5][c];
        F2PK(GR, br_, br_);
        F2PK(GZ, bz_, bz_);
        F2PK(GIN, bn_i, bn_i);
        F2PK(GHN, bn_h, bn_h);
    }

    float h00 = 0.f, h01 = 0.f, h10 = 0.f, h11 = 0.f;
    for (int t = 0; t < TT; t++) {
        S.s_h[w][0][c] = make_float2(h00, h01);
        S.s_h[w][1][c] = make_float2(h10, h11);
        __syncwarp();

        u64 gr0 = GR, gz0 = GZ, gin0 = GIN, ghn0 = GHN;
        u64 gr1 = GR, gz1 = GZ, gin1 = GIN, ghn1 = GHN;
#pragma unroll
        for (int hh = 0; hh < 32; hh++) {
            u64 xv0 = *(const u64*)&S.s_tr[nl0][t][hh];
            u64 xv1 = *(const u64*)&S.s_tr[nl1][t][hh];
            u64 hv0 = *(const u64*)&S.s_h[w][0][hh];
            u64 hv1 = *(const u64*)&S.s_h[w][1][hh];
            float4 wA = S.sWA[hh][c];
            float2 wB = S.sWB[hh][c];
            u64 wir, whr, wiz, whz, win, whn;
            F2PK(wir, wA.x, wA.x);
            F2PK(whr, wA.y, wA.y);
            F2PK(wiz, wA.z, wA.z);
            F2PK(whz, wA.w, wA.w);
            F2PK(win, wB.x, wB.x);
            F2PK(whn, wB.y, wB.y);
            F2FMA(gr0, xv0, wir, gr0);
            F2FMA(gr0, hv0, whr, gr0);
            F2FMA(gz0, xv0, wiz, gz0);
            F2FMA(gz0, hv0, whz, gz0);
            F2FMA(gin0, xv0, win, gin0);
            F2FMA(ghn0, hv0, whn, ghn0);
            F2FMA(gr1, xv1, wir, gr1);
            F2FMA(gr1, hv1, whr, gr1);
            F2FMA(gz1, xv1, wiz, gz1);
            F2FMA(gz1, hv1, whz, gz1);
            F2FMA(gin1, xv1, win, gin1);
            F2FMA(ghn1, hv1, whn, ghn1);
        }
#define GRU_OUT2(GRp, GZp, GINp, GHNp, H0, H1, N)                           \
        do {                                                                \
            float r0_, r1_, z0_, z1_, i0_, i1_, hn0_, hn1_;                 \
            F2UNPK(r0_, r1_, GRp);                                          \
            F2UNPK(z0_, z1_, GZp);                                          \
            F2UNPK(i0_, i1_, GINp);                                         \
            F2UNPK(hn0_, hn1_, GHNp);                                       \
            {                                                               \
                float r = 1.f / (1.f + __expf(-r0_));                       \
                float z = 1.f / (1.f + __expf(-z0_));                       \
                float pre = i0_ + r * hn0_;                                 \
                float e2 = __expf(-2.f * pre);                              \
                float nn_ = 2.f / (1.f + e2) - 1.f;                         \
                H0 = (1.f - z) * nn_ + z * H0;                              \
                out[((long)(0 * TT + t) * NN + (N)) * 32 + c] = H0;         \
            }                                                               \
            {                                                               \
                float r = 1.f / (1.f + __expf(-r1_));                       \
                float z = 1.f / (1.f + __expf(-z1_));                       \
                float pre = i1_ + r * hn1_;                                 \
                float e2 = __expf(-2.f * pre);                              \
                float nn_ = 2.f / (1.f + e2) - 1.f;                         \
                H1 = (1.f - z) * nn_ + z * H1;                              \
                out[((long)(1 * TT + t) * NN + (N)) * 32 + c] = H1;         \
            }                                                               \
        } while (0)
        GRU_OUT2(gr0, gz0, gin0, ghn0, h00, h01, n0);
        GRU_OUT2(gr1, gz1, gin1, ghn1, h10, h11, n1);
#undef GRU_OUT2
        __syncwarp();
    }

    // epilogue: re-zero per-node counters for the NEXT replay
    if (lane < 3) g_loop_sum[n0 * 3 + lane] = 0.f;
    else if (lane == 3) g_cursor[n0] = 0;
    else if (lane >= 4 && lane < 7) g_loop_sum[n1 * 3 + (lane - 4)] = 0.f;
    else if (lane == 7) g_cursor[n1] = 0;
}

// ---------------- launch: 3 kernels, xlr forked ----------------
extern "C" void kernel_launch(void* const* d_in, const int* in_sizes, int n_in,
                              void* d_out, int out_size) {
    const float* x        = (const float*)d_in[0];
    const int*   ei       = (const int*)d_in[1];
    const float* eattr    = (const float*)d_in[2];
    const float* W_l      = (const float*)d_in[3];
    const float* b_l      = (const float*)d_in[4];
    const float* W_r      = (const float*)d_in[5];
    const float* b_r      = (const float*)d_in[6];
    const float* W_e      = (const float*)d_in[7];
    const float* att      = (const float*)d_in[8];
    const float* bias_gat = (const float*)d_in[9];
    const float* W_ih     = (const float*)d_in[10];
    const float* W_hh     = (const float*)d_in[11];
    const float* b_ih     = (const float*)d_in[12];
    const float* b_hh     = (const float*)d_in[13];
    float* out = (float*)d_out;

    static cudaStream_t s1 = nullptr;
    static cudaEvent_t eRoot = nullptr, eXlr = nullptr;
    if (s1 == nullptr) {
        cudaStreamCreateWithFlags(&s1, cudaStreamNonBlocking);
        cudaEventCreateWithFlags(&eRoot, cudaEventDisableTiming);
        cudaEventCreateWithFlags(&eXlr, cudaEventDisableTiming);
        cudaFuncSetAttribute(k_xlr, cudaFuncAttributeMaxDynamicSharedMemorySize,
                             XCH * XPAD * (int)sizeof(float));
        cudaFuncSetAttribute(k_gatgru, cudaFuncAttributeMaxDynamicSharedMemorySize,
                             (int)sizeof(GGSmem));
    }

    cudaEventRecord(eRoot, 0);
    cudaStreamWaitEvent(s1, eRoot, 0);
    k_xlr<<<SNAP * NN / XCH, 256, XCH * XPAD * sizeof(float), s1>>>(x, W_l, b_l, W_r, b_r);
    cudaEventRecord(eXlr, s1);

    k_build<<<(EE + 255) / 256, 256>>>(ei, eattr);

    cudaStreamWaitEvent(0, eXlr, 0);
    k_gatgru<<<NN / 16, 256, sizeof(GGSmem)>>>(W_e, att, bias_gat, W_ih, W_hh, b_ih, b_hh, out);
}